// round 13
// baseline (speedup 1.0000x reference)
#include <cuda_runtime.h>
#include <math.h>
#include <stdint.h>

#define BATCH 128
#define SEQ   512
#define DIM   768
#define NCLS  9
#define ROWS  (BATCH * SEQ)   // 65536
#define D4    (DIM / 4)       // 192
#define NCHUNK 64             // 8 steps per chunk, covers t=1..512 (t=512 padded)

// ---- dynamic smem layout (aliased across phases) ----
// gemm phase:
#define OFF_WS   0            // 27648  W as float4
#define OFF_BS   27648        // 64
// crf phase (reuses the same buffer after a barrier):
#define OFF_EE   0            // 18432
#define OFF_B8   18432        // 20736
#define OFF_TAG  39168        // 2048
#define OFF_MSK  41216        // 2064 (SEQ+1 ints, padded)
#define OFF_TRT  43280        // 432
#define OFF_TRS  43712        // 336
#define OFF_ST   44048        // 48
#define OFF_EN   44096        // 48
#define SMEM_DYN 44160

__device__ float g_llh[BATCH];
__device__ int   g_cnt[BATCH];   // per-batch gemm-slab completion; self-resets
__device__ int   g_done;         // crf completion; self-resets

// ---------------------------------------------------------------------------
// Fused slab kernel. grid = 1024 blocks x 256 threads, 4 blocks/SM.
//  Part 1 (all blocks): gemm of 64 rows (R8-proven scalar formulation).
//  Part 2 (slab==7 blocks): after all 8 slabs of this batch are done,
//  run the full CRF for the batch (R8-proven formulation), overlapped with
//  other blocks' gemm work.
// ---------------------------------------------------------------------------
__global__ __launch_bounds__(256, 4) void fused_kernel(
    const float4* __restrict__ feat4,
    const int*    __restrict__ labels,
    const int*    __restrict__ mask,
    const float*  __restrict__ W,
    const float*  __restrict__ bias,
    const float*  __restrict__ start_t,
    const float*  __restrict__ end_t,
    const float*  __restrict__ trans,
    float*        __restrict__ out)
{
    extern __shared__ char smem[];
    __shared__ float num_sh, den_sh;
    __shared__ int   isLast;
    __shared__ float wsred[4];

    const int tid  = threadIdx.x;
    const int warp = tid >> 5;
    const int lane = tid & 31;
    const int li   = lane & 7;   // d-chunk within group
    const int g    = lane >> 3;  // group (0..3), 2 rows each

    const int b    = blockIdx.x >> 3;
    const int slab = blockIdx.x & 7;

    float* logits = out + 1;

    // ======================= Part 1: GEMM (64 rows) =======================
    {
        float4* Ws4 = (float4*)(smem + OFF_WS);
        float*  bS  = (float*)(smem + OFF_BS);

        const float4* W4 = (const float4*)W;
        for (int i = tid; i < NCLS * D4; i += 256) Ws4[i] = W4[i];
        if (tid < NCLS) bS[tid] = bias[tid];
        __syncthreads();

        const int rowa = blockIdx.x * 64 + warp * 8 + g * 2;
        const int rowb = rowa + 1;

        float acc[NCLS][2];
#pragma unroll
        for (int n = 0; n < NCLS; ++n) { acc[n][0] = 0.f; acc[n][1] = 0.f; }

        const float4* fa = feat4 + (size_t)rowa * D4;
        const float4* fb = feat4 + (size_t)rowb * D4;

#pragma unroll 2
        for (int k = 0; k < 24; ++k) {
            const int idx = k * 8 + li;          // 0..191
            const float4 a  = fa[idx];
            const float4 bv = fb[idx];
#pragma unroll
            for (int n = 0; n < NCLS; ++n) {
                const float4 w = Ws4[n * D4 + idx];
                acc[n][0] = fmaf(a.x,  w.x, fmaf(a.y,  w.y, fmaf(a.z,  w.z, fmaf(a.w,  w.w, acc[n][0]))));
                acc[n][1] = fmaf(bv.x, w.x, fmaf(bv.y, w.y, fmaf(bv.z, w.z, fmaf(bv.w, w.w, acc[n][1]))));
            }
        }

#pragma unroll
        for (int n = 0; n < NCLS; ++n) {
#pragma unroll
            for (int off = 4; off; off >>= 1) {
                acc[n][0] += __shfl_down_sync(0xffffffffu, acc[n][0], off, 8);
                acc[n][1] += __shfl_down_sync(0xffffffffu, acc[n][1], off, 8);
            }
        }

        if (li == 0) {
#pragma unroll
            for (int n = 0; n < NCLS; ++n) {
                logits[(size_t)rowa * NCLS + n] = acc[n][0] + bS[n];
                logits[(size_t)rowb * NCLS + n] = acc[n][1] + bS[n];
            }
        }
    }

    // publish slab completion (canonical fence pattern)
    __threadfence();
    __syncthreads();
    if (tid == 0) atomicAdd(&g_cnt[b], 1);

    if (slab != 7) return;

    // ================== Part 2: CRF for batch b (executor) ==================
    // wait for all 8 slabs of this batch
    if (tid == 0) {
        while (atomicAdd(&g_cnt[b], 0) < 8) __nanosleep(64);
    }
    __syncthreads();

    float* EE   = (float*)(smem + OFF_EE);
    float* B8   = (float*)(smem + OFF_B8);
    int*   tagS = (int*)(smem + OFF_TAG);
    int*   mS   = (int*)(smem + OFF_MSK);
    float* trT  = (float*)(smem + OFF_TRT);
    float* trS  = (float*)(smem + OFF_TRS);
    float* stS  = (float*)(smem + OFF_ST);
    float* enS  = (float*)(smem + OFF_EN);

    const float* lgb = logits + (size_t)b * SEQ * NCLS;

    // ---- Phase A: staging (logits via L2 to dodge any L1 staleness) ----
    for (int i = tid; i < SEQ * NCLS; i += 256)
        EE[i] = __expf(__ldcg(lgb + i));
    for (int i = tid; i < SEQ; i += 256) {
        const int lab = labels[(size_t)b * SEQ + i];
        tagS[i] = (lab == -100) ? 0 : lab;
        mS[i]   = (mask[(size_t)b * SEQ + i] != 0) ? 1 : 0;
    }
    if (tid == 0) { mS[SEQ] = 0; g_cnt[b] = 0; }   // pad + counter reset (replay-safe)
    if (tid < NCLS * NCLS) {
        const float tv = trans[tid];
        trS[tid] = tv;
        const int i = tid / NCLS, k = tid % NCLS;
        trT[k * 12 + i] = __expf(tv);              // trT[k][i] = exp(trans[i][k])
    }
    if (tid < NCLS) { stS[tid] = start_t[tid]; enS[tid] = end_t[tid]; }
    __syncthreads();

    // ---- Phase B: build B8 (576 column tasks) ----
    for (int task = tid; task < NCHUNK * NCLS; task += 256) {
        const int c = task / NCLS;
        const int j = task - c * NCLS;
        float v[NCLS];
#pragma unroll
        for (int i = 0; i < NCLS; ++i) v[i] = (i == j) ? 1.f : 0.f;

        for (int s = 7; s >= 0; --s) {
            const int t = 8 * c + 1 + s;           // 1..512
            if (mS[t]) {
                const float* eT = &EE[t * NCLS];
                float4 va = make_float4(0.f, 0.f, 0.f, 0.f);
                float4 vb = make_float4(0.f, 0.f, 0.f, 0.f);
                float  v8 = 0.f;
#pragma unroll
                for (int k = 0; k < NCLS; ++k) {
                    const float u = eT[k] * v[k];
                    const float4 t0 = *reinterpret_cast<const float4*>(trT + k * 12 + 0);
                    const float4 t1 = *reinterpret_cast<const float4*>(trT + k * 12 + 4);
                    const float  t2 = trT[k * 12 + 8];
                    va.x = fmaf(t0.x, u, va.x); va.y = fmaf(t0.y, u, va.y);
                    va.z = fmaf(t0.z, u, va.z); va.w = fmaf(t0.w, u, va.w);
                    vb.x = fmaf(t1.x, u, vb.x); vb.y = fmaf(t1.y, u, vb.y);
                    vb.z = fmaf(t1.z, u, vb.z); vb.w = fmaf(t1.w, u, vb.w);
                    v8   = fmaf(t2,   u, v8);
                }
                v[0] = va.x; v[1] = va.y; v[2] = va.z; v[3] = va.w;
                v[4] = vb.x; v[5] = vb.y; v[6] = vb.z; v[7] = vb.w;
                v[8] = v8;
            }
        }
#pragma unroll
        for (int i = 0; i < NCLS; ++i)
            B8[c * 81 + i * NCLS + j] = v[i];
    }
    __syncthreads();

    // ---- Phase C: 64-step serial scan (warp 0) + numerator (warp 1) ----
    if (warp == 0) {
        const int j = (lane < NCLS) ? lane : 0;
        float p = (lane < NCLS) ? __expf(stS[j] + __ldcg(lgb + j)) : 0.f;
        float clog = 0.f;

        float bcol[NCLS];
#pragma unroll
        for (int i = 0; i < NCLS; ++i) bcol[i] = B8[i * NCLS + j];

        for (int ch = 0; ch < NCHUNK; ++ch) {
            float nb[NCLS];
            if (ch < NCHUNK - 1) {
                const float* base = B8 + (ch + 1) * 81 + j;
#pragma unroll
                for (int i = 0; i < NCLS; ++i) nb[i] = base[i * NCLS];
            }

            const float p0 = __shfl_sync(0xffffffffu, p, 0);
            const float p1 = __shfl_sync(0xffffffffu, p, 1);
            const float p2 = __shfl_sync(0xffffffffu, p, 2);
            const float p3 = __shfl_sync(0xffffffffu, p, 3);
            const float p4 = __shfl_sync(0xffffffffu, p, 4);
            const float p5 = __shfl_sync(0xffffffffu, p, 5);
            const float p6 = __shfl_sync(0xffffffffu, p, 6);
            const float p7 = __shfl_sync(0xffffffffu, p, 7);
            const float p8 = __shfl_sync(0xffffffffu, p, 8);

            const float s0 = fmaf(p2, bcol[2], fmaf(p1, bcol[1], p0 * bcol[0]));
            const float s1 = fmaf(p5, bcol[5], fmaf(p4, bcol[4], p3 * bcol[3]));
            const float s2 = fmaf(p8, bcol[8], fmaf(p7, bcol[7], p6 * bcol[6]));
            float pn = (s0 + s1) + s2;

            if (ch & 1) {
                const float sv = __shfl_sync(0xffffffffu, pn, 0);
                pn *= __frcp_rn(sv);
                clog += __logf(sv);
            }
            p = pn;
#pragma unroll
            for (int i = 0; i < NCLS; ++i) bcol[i] = nb[i];
        }

        float v = (lane < NCLS) ? p * __expf(enS[j]) : 0.f;
#pragma unroll
        for (int off = 16; off; off >>= 1)
            v += __shfl_xor_sync(0xffffffffu, v, off);
        if (lane == 0) den_sh = clog + __logf(v);
    }
    else if (warp == 1) {
        float sc = 0.f;
        int   cnt = 0;
        for (int t = lane; t < SEQ; t += 32) {
            const int mt = mS[t];
            cnt += mt;
            if (t >= 1 && mt) {
                const int cur = tagS[t];
                const int prv = tagS[t - 1];
                sc += __ldcg(lgb + t * NCLS + cur) + trS[prv * NCLS + cur];
            }
        }
#pragma unroll
        for (int off = 16; off; off >>= 1) {
            sc  += __shfl_xor_sync(0xffffffffu, sc,  off);
            cnt += __shfl_xor_sync(0xffffffffu, cnt, off);
        }
        if (lane == 0) {
            const int first = tagS[0];
            sc += stS[first] + __ldcg(lgb + first);
            sc += enS[tagS[cnt - 1]];
            num_sh = sc;
        }
    }

    __syncthreads();

    // ---- Phase D: publish llh; last executor reduces to the loss ----
    if (tid == 0) {
        g_llh[b] = num_sh - den_sh;
        __threadfence();
        const int old = atomicAdd(&g_done, 1);
        isLast = (old == BATCH - 1) ? 1 : 0;
    }
    __syncthreads();

    if (isLast) {
        if (tid < 128) {
            float v = g_llh[tid];
#pragma unroll
            for (int off = 16; off; off >>= 1)
                v += __shfl_xor_sync(0xffffffffu, v, off);
            if (lane == 0) wsred[warp] = v;
        }
        __syncthreads();
        if (tid == 0) {
            const float tot = (wsred[0] + wsred[1]) + (wsred[2] + wsred[3]);
            out[0] = -tot / (float)BATCH;
            g_done = 0;   // reset for next graph replay
        }
    }
}

extern "C" void kernel_launch(void* const* d_in, const int* in_sizes, int n_in,
                              void* d_out, int out_size)
{
    const float4* feat4  = (const float4*)d_in[0];
    const int*    labels = (const int*)d_in[1];
    const int*    mask   = (const int*)d_in[2];
    const float*  W      = (const float*)d_in[3];
    const float*  bias   = (const float*)d_in[4];
    const float*  st     = (const float*)d_in[5];
    const float*  en     = (const float*)d_in[6];
    const float*  tr     = (const float*)d_in[7];

    float* out = (float*)d_out;

    fused_kernel<<<ROWS / 64, 256, SMEM_DYN>>>(feat4, labels, mask, W, bias,
                                               st, en, tr, out);
}